// round 4
// baseline (speedup 1.0000x reference)
#include <cuda_runtime.h>
#include <cuda_bf16.h>
#include <math.h>

// Problem constants (B, N, M, C, S = 4, 16384, 128, 128, 512)
#define BB    4
#define NPTS  16384
#define MBOX  128
#define CFEAT 128
#define SSAMP 512
#define ROWW  (3 + CFEAT)            // 131 floats per pooled row
#define NBOX  (BB * MBOX)            // 512
#define BOXFLOATS (SSAMP * ROWW)     // 67072 floats per box output tile

// ---- Kernel A config ----
#define A_THREADS 512
#define A_WARPS   (A_THREADS / 32)   // 16
#define A_SEG     (NPTS / A_WARPS)   // 1024
#define A_ITERS   (A_SEG / 32)       // 32

// ---- Kernel B config ----
#define B_THREADS 256
#define SLICES    8                  // CTAs per box in kernel B
#define SLICE_FLOATS (BOXFLOATS / SLICES)      // 8384
#define SLICE_VEC4   (SLICE_FLOATS / 4)        // 2096

// Scratch: resolved source index per output row (wrap already applied; -1 = empty box)
__device__ int g_src[NBOX * SSAMP];

// ============================================================================
// Kernel A: per-box ordered compaction + wrap resolution + flag
// ============================================================================
__global__ __launch_bounds__(A_THREADS)
void roipool3d_select(const float* __restrict__ points,   // (B, N, 3)
                      const float* __restrict__ boxes,    // (B, M, 7)
                      float* __restrict__ out,            // flags at tail
                      long long flag_off)
{
    const int bm = blockIdx.x;
    const int b  = bm >> 7;

    const float* box = boxes + (size_t)bm * 7;
    const float cx = box[0];
    const float cy = box[1];
    const float dz = box[5];
    const float cz = box[2] + 0.5f * dz;
    const float dx = box[3];
    const float dy = box[4];
    const float rz = box[6];
    const float cosa = cosf(-rz);
    const float sina = sinf(-rz);
    const float hx = 0.5f * dx;
    const float hy = 0.5f * dy;
    const float hz = 0.5f * dz;

    __shared__ int s_buf[A_WARPS][SSAMP];   // 32 KB
    __shared__ int s_cnt[A_WARPS];
    __shared__ int s_list[SSAMP];

    const int tid  = threadIdx.x;
    const int wid  = tid >> 5;
    const int lane = tid & 31;
    const unsigned lmask_lt = (1u << lane) - 1u;

    const float* pts = points + (size_t)b * NPTS * 3;

    // Warp-autonomous ordered compaction over contiguous segments
    {
        const int seg_start = wid * A_SEG;
        int wcnt = 0;

        #pragma unroll 4
        for (int it = 0; it < A_ITERS; ++it) {
            if (wcnt >= SSAMP) break;

            const int i = seg_start + it * 32 + lane;
            const float px = pts[i * 3 + 0];
            const float py = pts[i * 3 + 1];
            const float pz = pts[i * 3 + 2];

            const float sx = px - cx;
            const float sy = py - cy;
            const float lx = sx * cosa - sy * sina;
            const float ly = sx * sina + sy * cosa;

            const bool in =
                (fabsf(pz - cz) <= hz) &&
                (fabsf(lx) < hx) &&
                (fabsf(ly) < hy);

            const unsigned ball = __ballot_sync(0xffffffffu, in);
            const int r = wcnt + __popc(ball & lmask_lt);
            if (in && r < SSAMP) s_buf[wid][r] = i;
            wcnt += __popc(ball);
        }
        if (lane == 0) s_cnt[wid] = wcnt;
    }
    __syncthreads();

    // Concat per-warp buffers (warp order == global point-index order)
    int total = 0;
    int off   = 0;
    #pragma unroll
    for (int w = 0; w < A_WARPS; ++w) {
        const int c = s_cnt[w];
        off   += (w < wid) ? c : 0;
        total += c;
    }
    {
        const int stored = min(s_cnt[wid], SSAMP);
        for (int k = lane; k < stored; k += 32) {
            const int g = off + k;
            if (g < SSAMP) s_list[g] = s_buf[wid][k];
        }
    }
    __syncthreads();

    const int cnt = total;

    // Resolve wrap-around once: g_src[bm][s] = list[s % cnt]  (-1 if empty)
    {
        const int s = tid;   // A_THREADS == SSAMP
        int v;
        if (cnt == 0)            v = -1;
        else if (cnt >= SSAMP)   v = s_list[s];
        else                     v = s_list[s % cnt];
        g_src[bm * SSAMP + s] = v;
    }

    if (tid == 0)
        out[flag_off + bm] = (cnt == 0) ? 1.0f : 0.0f;
}

// ============================================================================
// Kernel B: massively parallel gather + vectorized store
// grid = NBOX * SLICES; each CTA writes one contiguous 8384-float slice.
// ============================================================================
__global__ __launch_bounds__(B_THREADS)
void roipool3d_write(const float* __restrict__ points,   // (B, N, 3)
                     const float* __restrict__ feats,    // (B, N, C)
                     float* __restrict__ out)
{
    const int bx    = blockIdx.x;
    const int bm    = bx >> 3;            // / SLICES
    const int slice = bx & (SLICES - 1);
    const int b     = bm >> 7;

    const int*   src_tab = g_src + bm * SSAMP;
    const float* pts     = points + (size_t)b * NPTS * 3;
    const float* fbase   = feats + (size_t)b * NPTS * CFEAT;

    float4* oslice = (float4*)(out + (size_t)bm * BOXFLOATS + slice * SLICE_FLOATS);
    const int qbase = slice * SLICE_FLOATS;   // local float offset within box tile

    for (int idx = threadIdx.x; idx < SLICE_VEC4; idx += B_THREADS) {
        const int q0 = qbase + idx * 4;       // local offset of first element
        int s = q0 / ROWW;                    // constant-divisor -> mul/shift
        int e = q0 - s * ROWW;

        int src = __ldg(src_tab + s);

        float4 v;
        float* vv = (float*)&v;
        #pragma unroll
        for (int k = 0; k < 4; ++k) {
            float val;
            if (src < 0) {
                val = 0.0f;
            } else if (e < 3) {
                val = __ldg(pts + src * 3 + e);
            } else {
                val = __ldg(fbase + (size_t)src * CFEAT + (e - 3));
            }
            vv[k] = val;
            if (++e == ROWW) {                // row boundary inside this float4
                e = 0;
                ++s;
                src = __ldg(src_tab + s);
            }
        }
        __stcs(oslice + idx, v);
    }
}

extern "C" void kernel_launch(void* const* d_in, const int* in_sizes, int n_in,
                              void* d_out, int out_size)
{
    const float* points = (const float*)d_in[0];   // (B, N, 3)
    const float* feats  = (const float*)d_in[1];   // (B, N, C)
    const float* boxes  = (const float*)d_in[2];   // (B, M, 7)
    float* out = (float*)d_out;

    const long long flag_off = (long long)out_size - (long long)NBOX;

    roipool3d_select<<<NBOX, A_THREADS>>>(points, boxes, out, flag_off);
    roipool3d_write<<<NBOX * SLICES, B_THREADS>>>(points, feats, out);
}

// round 5
// speedup vs baseline: 1.0799x; 1.0799x over previous
#include <cuda_runtime.h>
#include <cuda_bf16.h>
#include <math.h>

// Problem constants (B, N, M, C, S = 4, 16384, 128, 128, 512)
#define BB    4
#define NPTS  16384
#define MBOX  128
#define CFEAT 128
#define SSAMP 512
#define ROWW  (3 + CFEAT)            // 131 floats per pooled row
#define NBOX  (BB * MBOX)            // 512
#define BOXFLOATS (SSAMP * ROWW)     // 67072 floats per box tile (divisible by 4)

#define NTHREADS 512
#define NWARPS   (NTHREADS / 32)     // 16
#define SEG      (NPTS / NWARPS)     // 1024
#define ITERS    (SEG / 32)          // 32

__global__ __launch_bounds__(NTHREADS)
void roipool3d_kernel(const float* __restrict__ points,   // (B, N, 3)
                      const float* __restrict__ feats,    // (B, N, C)
                      const float* __restrict__ boxes,    // (B, M, 7)
                      float* __restrict__ out,            // (B,M,S,131) then flags (B,M)
                      long long flag_off)
{
    const int bm = blockIdx.x;
    const int b  = bm >> 7;

    // --- Box parameters ---
    const float* box = boxes + (size_t)bm * 7;
    const float cx = box[0];
    const float cy = box[1];
    const float dz = box[5];
    const float cz = box[2] + 0.5f * dz;
    const float dx = box[3];
    const float dy = box[4];
    const float rz = box[6];
    const float cosa = cosf(-rz);
    const float sina = sinf(-rz);
    const float hx = 0.5f * dx;
    const float hy = 0.5f * dy;
    const float hz = 0.5f * dz;

    __shared__ int s_buf[NWARPS][SSAMP];   // 32 KB: per-warp ordered buffers
    __shared__ int s_cnt[NWARPS];
    __shared__ int s_src[SSAMP];           // wrap-resolved source index per row

    const int tid  = threadIdx.x;
    const int wid  = tid >> 5;
    const int lane = tid & 31;
    const unsigned lmask_lt = (1u << lane) - 1u;

    const float* pts = points + (size_t)b * NPTS * 3;

    // --- Phase 1: warp-autonomous ordered compaction over contiguous segments ---
    {
        const int seg_start = wid * SEG;
        int wcnt = 0;

        #pragma unroll 4
        for (int it = 0; it < ITERS; ++it) {
            if (wcnt >= SSAMP) break;      // local rank >= S can never be used

            const int i = seg_start + it * 32 + lane;
            const float px = pts[i * 3 + 0];
            const float py = pts[i * 3 + 1];
            const float pz = pts[i * 3 + 2];

            const float sx = px - cx;
            const float sy = py - cy;
            const float lx = sx * cosa - sy * sina;
            const float ly = sx * sina + sy * cosa;

            const bool in =
                (fabsf(pz - cz) <= hz) &&
                (fabsf(lx) < hx) &&
                (fabsf(ly) < hy);

            const unsigned ball = __ballot_sync(0xffffffffu, in);
            const int r = wcnt + __popc(ball & lmask_lt);
            if (in && r < SSAMP) s_buf[wid][r] = i;
            wcnt += __popc(ball);
        }
        if (lane == 0) s_cnt[wid] = wcnt;
    }
    __syncthreads();

    // --- Merge + wrap resolution ---
    int total = 0;
    int off   = 0;
    #pragma unroll
    for (int w = 0; w < NWARPS; ++w) {
        const int c = s_cnt[w];
        off   += (w < wid) ? c : 0;
        total += c;
    }
    const int cnt = total;
    {
        // concat per-warp buffers into the low part of s_src (global order)
        const int stored = min(s_cnt[wid], SSAMP);
        for (int k = lane; k < stored; k += 32) {
            const int g = off + k;
            if (g < SSAMP) s_src[g] = s_buf[wid][k];
        }
    }
    __syncthreads();
    if (cnt > 0 && cnt < SSAMP) {
        // expand wrap-around in place: rows [cnt, S) copy from row % cnt
        for (int s = cnt + tid; s < SSAMP; s += NTHREADS)
            s_src[s] = s_src[s % cnt];
        __syncthreads();
    }

    // --- Phase 2: warp-per-row, aligned float4 stores ---
    float* o = out + (size_t)bm * BOXFLOATS;

    if (cnt == 0) {
        float4 z = make_float4(0.f, 0.f, 0.f, 0.f);
        float4* o4 = (float4*)o;
        for (int i = tid; i < BOXFLOATS / 4; i += NTHREADS)
            __stcs(o4 + i, z);
    } else {
        for (int s = wid; s < SSAMP; s += NWARPS) {
            const int src = s_src[s];
            const float* p = pts + src * 3;
            const float* f = feats + ((size_t)b * NPTS + src) * CFEAT;

            const int rbase = s * ROWW;                 // float offset within box tile
            const int pad   = (4 - (rbase & 3)) & 3;    // 0..3 leading scalars

            // leading scalars: elements e = 0..pad-1 (pad<=3 so these are coords/early feats)
            if (lane < pad) {
                const int e = lane;
                const float v = (e < 3) ? p[e] : f[e - 3];
                __stcs(o + rbase + e, v);
            }
            // one aligned float4 per lane: elements e = pad + 4*lane + k
            {
                const int e0 = pad + 4 * lane;
                float4 v;
                float* vv = (float*)&v;
                #pragma unroll
                for (int k = 0; k < 4; ++k) {
                    const int e = e0 + k;
                    vv[k] = (e < 3) ? p[e] : f[e - 3];
                }
                __stcs((float4*)(o + rbase + e0), v);
            }
            // tail scalars: elements e = pad+128 .. 130  (count = 3 - pad)
            if (lane < 3 - pad) {
                const int e = pad + 128 + lane;
                __stcs(o + rbase + e, f[e - 3]);
            }
        }
    }

    // --- Empty flag ---
    if (tid == 0)
        out[flag_off + bm] = (cnt == 0) ? 1.0f : 0.0f;
}

extern "C" void kernel_launch(void* const* d_in, const int* in_sizes, int n_in,
                              void* d_out, int out_size)
{
    const float* points = (const float*)d_in[0];   // (B, N, 3)
    const float* feats  = (const float*)d_in[1];   // (B, N, C)
    const float* boxes  = (const float*)d_in[2];   // (B, M, 7)
    float* out = (float*)d_out;

    const long long flag_off = (long long)out_size - (long long)NBOX;

    roipool3d_kernel<<<NBOX, NTHREADS>>>(points, feats, boxes, out, flag_off);
}